// round 1
// baseline (speedup 1.0000x reference)
#include <cuda_runtime.h>

// SelfAttention: B=4, H=W=64 (N=4096 tokens), C=F=128.
// out = softmax(Q K^T) V + x, Q/K/V = x @ W{q,k,v} + b.
// Round 0: fp32 SIMT baseline. QKV GEMM kernel + fused flash-attention kernel.

#define B_  4
#define N_  4096
#define C_  128
#define BQ_ 64
#define BK_ 64

// Scratch for projections (8 MB each) — device globals (no cudaMalloc allowed).
__device__ float g_q[(size_t)B_ * N_ * C_];
__device__ float g_k[(size_t)B_ * N_ * C_];
__device__ float g_v[(size_t)B_ * N_ * C_];

// ---------------------------------------------------------------------------
// QKV projection: rows = B*N = 16384 tokens, each projected by 3 [128,128] W.
// Block: 64 rows. smem: X tile (64x128) + one W (128x128) = 96 KB dynamic.
// Microtile 4 rows x 8 cols per thread; cols lane-interleaved (c = lane + 16j)
// so sW reads are conflict-free and sX reads broadcast.
// ---------------------------------------------------------------------------
__global__ __launch_bounds__(256, 2) void qkv_kernel(
    const float* __restrict__ x,
    const float* __restrict__ Wq, const float* __restrict__ bq,
    const float* __restrict__ Wk, const float* __restrict__ bk,
    const float* __restrict__ Wv, const float* __restrict__ bv)
{
    extern __shared__ float sm[];
    float* sX = sm;              // 64*128
    float* sW = sm + 64 * 128;   // 128*128

    const int tid  = threadIdx.x;
    const int row0 = blockIdx.x * 64;
    const int lane = tid & 15;
    const int r0   = (tid >> 4) * 4;

    // Load X tile (coalesced)
    #pragma unroll
    for (int i = 0; i < 32; i++) {
        int idx = tid + i * 256;
        sX[idx] = x[(size_t)row0 * 128 + idx];
    }

    const float* Ws[3]   = {Wq, Wk, Wv};
    const float* bias[3] = {bq, bk, bv};
    float* outs[3]       = {g_q, g_k, g_v};

    for (int p = 0; p < 3; p++) {
        __syncthreads();   // protect sW (and sX on first iter)
        const float* W = Ws[p];
        #pragma unroll
        for (int i = 0; i < 64; i++) {
            int idx = tid + i * 256;
            sW[idx] = W[idx];
        }
        __syncthreads();

        float acc[4][8];
        #pragma unroll
        for (int i = 0; i < 4; i++)
            #pragma unroll
            for (int j = 0; j < 8; j++) acc[i][j] = 0.f;

        #pragma unroll 8
        for (int k = 0; k < 128; k++) {
            float a[4], bb[8];
            #pragma unroll
            for (int i = 0; i < 4; i++) a[i] = sX[(r0 + i) * 128 + k];
            #pragma unroll
            for (int j = 0; j < 8; j++) bb[j] = sW[k * 128 + lane + 16 * j];
            #pragma unroll
            for (int i = 0; i < 4; i++)
                #pragma unroll
                for (int j = 0; j < 8; j++)
                    acc[i][j] += a[i] * bb[j];
        }

        float* o = outs[p];
        const float* bp = bias[p];
        #pragma unroll
        for (int j = 0; j < 8; j++) {
            float bj = bp[lane + 16 * j];
            #pragma unroll
            for (int i = 0; i < 4; i++)
                o[(size_t)(row0 + r0 + i) * 128 + lane + 16 * j] = acc[i][j] + bj;
        }
    }
}

// ---------------------------------------------------------------------------
// Fused flash attention (unscaled logits) + residual.
// Grid: 256 blocks = 4 batches * 64 q-tiles of 64 rows. 256 threads.
// smem: sQ/sK/sV [64][129] (pad 1 -> conflict-free row-strided reads),
//       sP [64][65]. Total 113 KB -> 2 CTAs/SM.
// Per-thread: 4 q-rows x 8 out-cols of O in registers; online softmax with
// 16-lane shuffle reductions (the 16 threads of one tid/16 group own a row).
// ---------------------------------------------------------------------------
__global__ __launch_bounds__(256, 2) void attn_kernel(
    const float* __restrict__ x, float* __restrict__ out)
{
    extern __shared__ float sm[];
    float* sQ = sm;                    // 64*129
    float* sK = sQ + 64 * 129;
    float* sV = sK + 64 * 129;
    float* sP = sV + 64 * 129;         // 64*65

    const int tid  = threadIdx.x;
    const int b    = blockIdx.x >> 6;
    const int qt   = blockIdx.x & 63;
    const int q0   = qt * 64;
    const int lane = tid & 15;
    const int r0   = (tid >> 4) * 4;

    const float* qg = g_q + (size_t)b * N_ * C_;
    const float* kg = g_k + (size_t)b * N_ * C_;
    const float* vg = g_v + (size_t)b * N_ * C_;

    // Load Q tile
    #pragma unroll
    for (int i = 0; i < 32; i++) {
        int idx = tid + i * 256;
        int r = idx >> 7, f = idx & 127;
        sQ[r * 129 + f] = qg[(size_t)(q0 + r) * 128 + f];
    }

    float m_[4], l_[4], O[4][8];
    #pragma unroll
    for (int i = 0; i < 4; i++) {
        m_[i] = -1e30f;
        l_[i] = 0.f;
        #pragma unroll
        for (int j = 0; j < 8; j++) O[i][j] = 0.f;
    }

    for (int kt = 0; kt < 64; kt++) {
        __syncthreads();   // prev PV done: safe to overwrite sK/sV/sP
        const int k0 = kt * 64;
        #pragma unroll
        for (int i = 0; i < 32; i++) {
            int idx = tid + i * 256;
            int r = idx >> 7, f = idx & 127;
            sK[r * 129 + f] = kg[(size_t)(k0 + r) * 128 + f];
            sV[r * 129 + f] = vg[(size_t)(k0 + r) * 128 + f];
        }
        __syncthreads();

        // ---- S = Q K^T (64x64 tile), 4x4 per thread, cols = lane + 16j ----
        float s[4][4];
        #pragma unroll
        for (int i = 0; i < 4; i++)
            #pragma unroll
            for (int j = 0; j < 4; j++) s[i][j] = 0.f;

        #pragma unroll 4
        for (int f = 0; f < 128; f++) {
            float a[4], bb[4];
            #pragma unroll
            for (int i = 0; i < 4; i++) a[i] = sQ[(r0 + i) * 129 + f];
            #pragma unroll
            for (int j = 0; j < 4; j++) bb[j] = sK[(lane + 16 * j) * 129 + f];
            #pragma unroll
            for (int i = 0; i < 4; i++)
                #pragma unroll
                for (int j = 0; j < 4; j++)
                    s[i][j] += a[i] * bb[j];
        }

        // ---- online softmax update ----
        #pragma unroll
        for (int i = 0; i < 4; i++) {
            float mx = s[i][0];
            #pragma unroll
            for (int j = 1; j < 4; j++) mx = fmaxf(mx, s[i][j]);
            #pragma unroll
            for (int off = 8; off >= 1; off >>= 1)
                mx = fmaxf(mx, __shfl_xor_sync(0xffffffffu, mx, off));
            float mnew  = fmaxf(m_[i], mx);
            float scale = __expf(m_[i] - mnew);
            m_[i] = mnew;

            float rs = 0.f;
            #pragma unroll
            for (int j = 0; j < 4; j++) {
                s[i][j] = __expf(s[i][j] - mnew);
                rs += s[i][j];
            }
            #pragma unroll
            for (int off = 8; off >= 1; off >>= 1)
                rs += __shfl_xor_sync(0xffffffffu, rs, off);
            l_[i] = l_[i] * scale + rs;

            #pragma unroll
            for (int j = 0; j < 8; j++) O[i][j] *= scale;
            #pragma unroll
            for (int j = 0; j < 4; j++)
                sP[(r0 + i) * 65 + lane + 16 * j] = s[i][j];
        }
        __syncthreads();

        // ---- O += P V (64x128), 4x8 per thread ----
        #pragma unroll 4
        for (int m = 0; m < 64; m++) {
            float a[4], bb[8];
            #pragma unroll
            for (int i = 0; i < 4; i++) a[i] = sP[(r0 + i) * 65 + m];
            #pragma unroll
            for (int j = 0; j < 8; j++) bb[j] = sV[m * 129 + lane + 16 * j];
            #pragma unroll
            for (int i = 0; i < 4; i++)
                #pragma unroll
                for (int j = 0; j < 8; j++)
                    O[i][j] += a[i] * bb[j];
        }
    }

    // ---- normalize + residual + store ----
    #pragma unroll
    for (int i = 0; i < 4; i++) {
        float inv = 1.f / l_[i];
        size_t rowbase = ((size_t)b * N_ + q0 + r0 + i) * 128;
        #pragma unroll
        for (int j = 0; j < 8; j++) {
            int c = lane + 16 * j;
            out[rowbase + c] = O[i][j] * inv + x[rowbase + c];
        }
    }
}

// ---------------------------------------------------------------------------
extern "C" void kernel_launch(void* const* d_in, const int* in_sizes, int n_in,
                              void* d_out, int out_size)
{
    (void)in_sizes; (void)n_in; (void)out_size;
    const float* x  = (const float*)d_in[0];
    const float* Wq = (const float*)d_in[1];
    const float* bq = (const float*)d_in[2];
    const float* Wk = (const float*)d_in[3];
    const float* bk = (const float*)d_in[4];
    const float* Wv = (const float*)d_in[5];
    const float* bv = (const float*)d_in[6];
    float* out = (float*)d_out;

    const int QKV_SMEM  = (64 * 128 + 128 * 128) * 4;                 // 98304
    const int ATTN_SMEM = (3 * 64 * 129 + 64 * 65) * 4;               // 115712

    cudaFuncSetAttribute(qkv_kernel,  cudaFuncAttributeMaxDynamicSharedMemorySize, QKV_SMEM);
    cudaFuncSetAttribute(attn_kernel, cudaFuncAttributeMaxDynamicSharedMemorySize, ATTN_SMEM);

    qkv_kernel<<<(B_ * N_) / 64, 256, QKV_SMEM>>>(x, Wq, bq, Wk, bk, Wv, bv);
    attn_kernel<<<B_ * (N_ / BQ_), 256, ATTN_SMEM>>>(x, out);
}

// round 6
// speedup vs baseline: 3.8646x; 3.8646x over previous
#include <cuda_runtime.h>
#include <cuda_bf16.h>
#include <cuda_fp16.h>
#include <cstdint>

// SelfAttention: B=4, N=4096, C=F=128. out = softmax(QK^T)V + x.
// Round 5: mma.sync flash attention (fix: K tile rows are 256B = 16 chunks;
// previous round only loaded 8 -> uninitialized smem -> NaN).

#define NB 4
#define NN 4096
#define NC 128
#define BQ 64
#define BK 64
#define NIT (NN / BK)   // 64

// ---------------- device globals (no cudaMalloc allowed) -------------------
__device__ __nv_bfloat16 g_qhi[(size_t)NB * NN * NC];
__device__ __nv_bfloat16 g_qlo[(size_t)NB * NN * NC];
__device__ __nv_bfloat16 g_khi[(size_t)NB * NN * NC];
__device__ __nv_bfloat16 g_klo[(size_t)NB * NN * NC];
__device__ __half        g_vt [(size_t)NB * NC * NN];   // V transposed [b][f][n]

// ---------------- smem layout (bytes, per buffer) ---------------------------
// K rows padded 128->136 bf16 (272B); Vt rows padded 64->72 fp16 (144B).
#define KROW 272
#define VROW 144
#define OFF_KHI 0
#define OFF_KLO 17408
#define OFF_VT  34816
#define BUF_SZ  53248
#define ATTN_SMEM (2 * BUF_SZ)   // 106496

// single shared extern symbol for the whole TU
extern __shared__ __align__(16) char smem_raw[];

// ---------------- helpers ----------------------------------------------------
__device__ __forceinline__ uint32_t smem_u32(const void* p) {
    uint32_t a;
    asm("{ .reg .u64 t; cvta.to.shared.u64 t, %1; cvt.u32.u64 %0, t; }"
        : "=r"(a) : "l"(p));
    return a;
}
__device__ __forceinline__ void cp16(uint32_t dst, const void* src) {
    asm volatile("cp.async.cg.shared.global [%0], [%1], 16;"
                 :: "r"(dst), "l"(src) : "memory");
}
__device__ __forceinline__ void cp_commit() {
    asm volatile("cp.async.commit_group;" ::: "memory");
}
template<int N> __device__ __forceinline__ void cp_wait() {
    asm volatile("cp.async.wait_group %0;" :: "n"(N) : "memory");
}
__device__ __forceinline__ void mma_bf16(float* d, const uint32_t* a,
                                         uint32_t b0, uint32_t b1) {
    asm volatile(
        "mma.sync.aligned.m16n8k16.row.col.f32.bf16.bf16.f32 "
        "{%0,%1,%2,%3}, {%4,%5,%6,%7}, {%8,%9}, {%0,%1,%2,%3};"
        : "+f"(d[0]), "+f"(d[1]), "+f"(d[2]), "+f"(d[3])
        : "r"(a[0]), "r"(a[1]), "r"(a[2]), "r"(a[3]), "r"(b0), "r"(b1));
}
__device__ __forceinline__ void mma_f16(float* d, const uint32_t* a,
                                        uint32_t b0, uint32_t b1) {
    asm volatile(
        "mma.sync.aligned.m16n8k16.row.col.f32.f16.f16.f32 "
        "{%0,%1,%2,%3}, {%4,%5,%6,%7}, {%8,%9}, {%0,%1,%2,%3};"
        : "+f"(d[0]), "+f"(d[1]), "+f"(d[2]), "+f"(d[3])
        : "r"(a[0]), "r"(a[1]), "r"(a[2]), "r"(a[3]), "r"(b0), "r"(b1));
}

// ---------------------------------------------------------------------------
// QKV projection (fp32 SIMT). Emits Q/K as bf16 hi/lo splits, V fp16 transposed.
// ---------------------------------------------------------------------------
__global__ __launch_bounds__(256, 2) void qkv_kernel(
    const float* __restrict__ x,
    const float* __restrict__ Wq, const float* __restrict__ bq,
    const float* __restrict__ Wk, const float* __restrict__ bk,
    const float* __restrict__ Wv, const float* __restrict__ bv)
{
    float* smf = reinterpret_cast<float*>(smem_raw);
    float* sX = smf;
    float* sW = smf + 64 * 128;

    const int tid  = threadIdx.x;
    const int row0 = blockIdx.x * 64;
    const int lane = tid & 15;
    const int r0   = (tid >> 4) * 4;

    #pragma unroll
    for (int i = 0; i < 32; i++) {
        int idx = tid + i * 256;
        sX[idx] = x[(size_t)row0 * 128 + idx];
    }

    const float* Ws[3]   = {Wq, Wk, Wv};
    const float* bias[3] = {bq, bk, bv};

    for (int p = 0; p < 3; p++) {
        __syncthreads();
        const float* W = Ws[p];
        #pragma unroll
        for (int i = 0; i < 64; i++) {
            int idx = tid + i * 256;
            sW[idx] = W[idx];
        }
        __syncthreads();

        float acc[4][8];
        #pragma unroll
        for (int i = 0; i < 4; i++)
            #pragma unroll
            for (int j = 0; j < 8; j++) acc[i][j] = 0.f;

        #pragma unroll 8
        for (int k = 0; k < 128; k++) {
            float a[4], bb[8];
            #pragma unroll
            for (int i = 0; i < 4; i++) a[i] = sX[(r0 + i) * 128 + k];
            #pragma unroll
            for (int j = 0; j < 8; j++) bb[j] = sW[k * 128 + lane + 16 * j];
            #pragma unroll
            for (int i = 0; i < 4; i++)
                #pragma unroll
                for (int j = 0; j < 8; j++)
                    acc[i][j] += a[i] * bb[j];
        }

        const float* bp = bias[p];
        #pragma unroll
        for (int j = 0; j < 8; j++) {
            int col = lane + 16 * j;
            float bj = bp[col];
            #pragma unroll
            for (int i = 0; i < 4; i++) {
                int token = row0 + r0 + i;
                float val = acc[i][j] + bj;
                size_t gi = (size_t)token * 128 + col;
                if (p == 0) {
                    __nv_bfloat16 h = __float2bfloat16(val);
                    g_qhi[gi] = h;
                    g_qlo[gi] = __float2bfloat16(val - __bfloat162float(h));
                } else if (p == 1) {
                    __nv_bfloat16 h = __float2bfloat16(val);
                    g_khi[gi] = h;
                    g_klo[gi] = __float2bfloat16(val - __bfloat162float(h));
                } else {
                    int bb_ = token >> 12, nn_ = token & 4095;
                    g_vt[((size_t)bb_ * 128 + col) * 4096 + nn_] = __float2half(val);
                }
            }
        }
    }
}

// ---------------------------------------------------------------------------
// Cooperative tile load (128 threads): Khi/Klo [64][128] bf16, Vt [128][64] f16.
// K row = 256B = 16 chunks of 16B -> 8 iterations x 128 threads (FIXED).
// Vt row = 128B = 8 chunks -> 8 iterations.
// ---------------------------------------------------------------------------
__device__ __forceinline__ void load_tiles(uint32_t dstb, int tid,
    const __nv_bfloat16* khb, const __nv_bfloat16* klb, const __half* vtb, int kt)
{
    const int k0 = kt * BK;
    #pragma unroll
    for (int i = 0; i < 8; i++) {
        int idx = tid + i * 128;           // 0..1023
        int row = idx >> 4, q = idx & 15;  // 64 rows x 16 chunks
        cp16(dstb + OFF_KHI + row * KROW + q * 16,
             khb + (size_t)(k0 + row) * NC + q * 8);
        cp16(dstb + OFF_KLO + row * KROW + q * 16,
             klb + (size_t)(k0 + row) * NC + q * 8);
    }
    #pragma unroll
    for (int i = 0; i < 8; i++) {
        int idx = tid + i * 128;           // 0..1023
        int row = idx >> 3, q = idx & 7;   // 128 rows x 8 chunks
        cp16(dstb + OFF_VT + row * VROW + q * 16,
             vtb + (size_t)row * NN + k0 + q * 8);
    }
    cp_commit();
}

// ---------------------------------------------------------------------------
// Flash attention with mma.sync. 256 CTAs (4 batches x 64 q-tiles), 128 thr.
// Warp w owns q rows [q0+16w, q0+16w+16). Online softmax in registers.
// ---------------------------------------------------------------------------
__global__ __launch_bounds__(128, 2) void attn_mma(
    const float* __restrict__ x, float* __restrict__ out)
{
    char* smc = smem_raw;
    const uint32_t sb = smem_u32(smc);
    const int tid  = threadIdx.x;
    const int warp = tid >> 5, lane = tid & 31;
    const int g    = lane >> 2, tig = lane & 3;
    const int b    = blockIdx.x >> 6;
    const int q0   = (blockIdx.x & 63) * BQ;
    const int qrow = q0 + warp * 16;

    // ---- Q fragments (hi/lo), loaded once ----
    uint32_t qh[8][4], ql[8][4];
    {
        const uint16_t* qhp = (const uint16_t*)g_qhi + ((size_t)b * NN + qrow) * NC;
        const uint16_t* qlp = (const uint16_t*)g_qlo + ((size_t)b * NN + qrow) * NC;
        #pragma unroll
        for (int ks = 0; ks < 8; ks++) {
            int c = ks * 16 + tig * 2;
            qh[ks][0] = *(const uint32_t*)(qhp + (size_t)g * NC + c);
            qh[ks][1] = *(const uint32_t*)(qhp + (size_t)(g + 8) * NC + c);
            qh[ks][2] = *(const uint32_t*)(qhp + (size_t)g * NC + c + 8);
            qh[ks][3] = *(const uint32_t*)(qhp + (size_t)(g + 8) * NC + c + 8);
            ql[ks][0] = *(const uint32_t*)(qlp + (size_t)g * NC + c);
            ql[ks][1] = *(const uint32_t*)(qlp + (size_t)(g + 8) * NC + c);
            ql[ks][2] = *(const uint32_t*)(qlp + (size_t)g * NC + c + 8);
            ql[ks][3] = *(const uint32_t*)(qlp + (size_t)(g + 8) * NC + c + 8);
        }
    }

    const __nv_bfloat16* khb = g_khi + (size_t)b * NN * NC;
    const __nv_bfloat16* klb = g_klo + (size_t)b * NN * NC;
    const __half*        vtb = g_vt  + (size_t)b * NC * NN;

    float O[16][4];
    #pragma unroll
    for (int n = 0; n < 16; n++)
        #pragma unroll
        for (int j = 0; j < 4; j++) O[n][j] = 0.f;
    float m0 = -1e30f, m1 = -1e30f, l0 = 0.f, l1 = 0.f;

    load_tiles(sb, tid, khb, klb, vtb, 0);

    for (int kt = 0; kt < NIT; kt++) {
        const int cur = kt & 1;
        if (kt + 1 < NIT) {
            load_tiles(sb + (cur ^ 1) * BUF_SZ, tid, khb, klb, vtb, kt + 1);
            cp_wait<1>();
        } else {
            cp_wait<0>();
        }
        __syncthreads();

        const char* buf = smc + cur * BUF_SZ;

        // ---- S = Q K^T : 3-pass split-bf16, 16x64 per warp ----
        float s[8][4];
        #pragma unroll
        for (int n = 0; n < 8; n++)
            #pragma unroll
            for (int j = 0; j < 4; j++) s[n][j] = 0.f;

        #pragma unroll
        for (int ks = 0; ks < 8; ks++) {
            const int coff = (ks * 16 + tig * 2) * 2;
            #pragma unroll
            for (int nb = 0; nb < 8; nb++) {
                const uint32_t* kh =
                    (const uint32_t*)(buf + OFF_KHI + (nb * 8 + g) * KROW + coff);
                const uint32_t* kl =
                    (const uint32_t*)(buf + OFF_KLO + (nb * 8 + g) * KROW + coff);
                uint32_t bh0 = kh[0], bh1 = kh[4];
                uint32_t bl0 = kl[0], bl1 = kl[4];
                mma_bf16(s[nb], qh[ks], bh0, bh1);
                mma_bf16(s[nb], qh[ks], bl0, bl1);
                mma_bf16(s[nb], ql[ks], bh0, bh1);
            }
        }

        // ---- online softmax (rows g and g+8; reduce over quad) ----
        float mx0 = -1e30f, mx1 = -1e30f;
        #pragma unroll
        for (int nb = 0; nb < 8; nb++) {
            mx0 = fmaxf(mx0, fmaxf(s[nb][0], s[nb][1]));
            mx1 = fmaxf(mx1, fmaxf(s[nb][2], s[nb][3]));
        }
        mx0 = fmaxf(mx0, __shfl_xor_sync(0xffffffffu, mx0, 1));
        mx0 = fmaxf(mx0, __shfl_xor_sync(0xffffffffu, mx0, 2));
        mx1 = fmaxf(mx1, __shfl_xor_sync(0xffffffffu, mx1, 1));
        mx1 = fmaxf(mx1, __shfl_xor_sync(0xffffffffu, mx1, 2));

        float mn0 = fmaxf(m0, mx0), mn1 = fmaxf(m1, mx1);
        float sc0 = __expf(m0 - mn0), sc1 = __expf(m1 - mn1);
        m0 = mn0; m1 = mn1;
        l0 *= sc0; l1 *= sc1;
        #pragma unroll
        for (int n = 0; n < 16; n++) {
            O[n][0] *= sc0; O[n][1] *= sc0;
            O[n][2] *= sc1; O[n][3] *= sc1;
        }

        // ---- P = exp(S-m) -> fp16 A-fragments; l from ROUNDED p ----
        uint32_t pf[4][4];
        #pragma unroll
        for (int kk = 0; kk < 4; kk++) {
            #pragma unroll
            for (int h = 0; h < 2; h++) {
                int nb = 2 * kk + h;
                __half2 ha = __floats2half2_rn(__expf(s[nb][0] - mn0),
                                               __expf(s[nb][1] - mn0));
                __half2 hb = __floats2half2_rn(__expf(s[nb][2] - mn1),
                                               __expf(s[nb][3] - mn1));
                float2 fa = __half22float2(ha);
                float2 fb = __half22float2(hb);
                l0 += fa.x + fa.y;
                l1 += fb.x + fb.y;
                pf[kk][0 + h * 2] = *reinterpret_cast<uint32_t*>(&ha);
                pf[kk][1 + h * 2] = *reinterpret_cast<uint32_t*>(&hb);
            }
        }

        // ---- O += P V (fp16), 16x128 per warp ----
        #pragma unroll
        for (int kk = 0; kk < 4; kk++) {
            const int coff = (kk * 16 + tig * 2) * 2;
            #pragma unroll
            for (int nb2 = 0; nb2 < 16; nb2++) {
                const uint32_t* vp =
                    (const uint32_t*)(buf + OFF_VT + (nb2 * 8 + g) * VROW + coff);
                mma_f16(O[nb2], pf[kk], vp[0], vp[4]);
            }
        }
        __syncthreads();
    }

    // ---- epilogue: reduce l over quad, normalize, add residual ----
    l0 += __shfl_xor_sync(0xffffffffu, l0, 1);
    l0 += __shfl_xor_sync(0xffffffffu, l0, 2);
    l1 += __shfl_xor_sync(0xffffffffu, l1, 1);
    l1 += __shfl_xor_sync(0xffffffffu, l1, 2);
    const float inv0 = 1.f / l0, inv1 = 1.f / l1;

    const size_t ra = ((size_t)b * NN + qrow + g) * NC;
    const size_t rb = ((size_t)b * NN + qrow + g + 8) * NC;
    #pragma unroll
    for (int nb2 = 0; nb2 < 16; nb2++) {
        int col = nb2 * 8 + tig * 2;
        float2 xa = *(const float2*)(x + ra + col);
        float2 xb = *(const float2*)(x + rb + col);
        float2 oa = { O[nb2][0] * inv0 + xa.x, O[nb2][1] * inv0 + xa.y };
        float2 ob = { O[nb2][2] * inv1 + xb.x, O[nb2][3] * inv1 + xb.y };
        *(float2*)(out + ra + col) = oa;
        *(float2*)(out + rb + col) = ob;
    }
}

// ---------------------------------------------------------------------------
extern "C" void kernel_launch(void* const* d_in, const int* in_sizes, int n_in,
                              void* d_out, int out_size)
{
    (void)in_sizes; (void)n_in; (void)out_size;
    const float* x  = (const float*)d_in[0];
    const float* Wq = (const float*)d_in[1];
    const float* bq = (const float*)d_in[2];
    const float* Wk = (const float*)d_in[3];
    const float* bk = (const float*)d_in[4];
    const float* Wv = (const float*)d_in[5];
    const float* bv = (const float*)d_in[6];
    float* out = (float*)d_out;

    const int QKV_SMEM = (64 * 128 + 128 * 128) * 4;   // 98304

    cudaFuncSetAttribute(qkv_kernel, cudaFuncAttributeMaxDynamicSharedMemorySize, QKV_SMEM);
    cudaFuncSetAttribute(attn_mma,   cudaFuncAttributeMaxDynamicSharedMemorySize, ATTN_SMEM);

    qkv_kernel<<<(NB * NN) / 64, 256, QKV_SMEM>>>(x, Wq, bq, Wk, bk, Wv, bv);
    attn_mma<<<NB * (NN / BQ), 128, ATTN_SMEM>>>(x, out);
}